// round 8
// baseline (speedup 1.0000x reference)
#include <cuda_runtime.h>
#include <cuda_bf16.h>
#include <math.h>
#include <stdint.h>

#define NODES 50000
#define NODES_PAD 50048            // 391 tiles * 128
#define EDGES 800000
#define NTILES 391

// ---------------- scratch (static device globals; no allocs allowed) ----------
// A matrices stored as bf16 triple-interleaved streams:
//   A pattern per original k: [hi, hi, lo]   B pattern: [hi, lo, hi]
//   plain GEMM over K''=3K then yields hi*hi + hi*lo + lo*hi  (3xBF16 split)
__device__ __align__(128) unsigned char g_a1[(size_t)NODES_PAD * 3072]; // [N][1536 bf16]: cols 0..767 agg, 768..1535 x
__device__ __align__(128) unsigned char g_a2[(size_t)NODES_PAD * 1536]; // [N][768 bf16] : h triples
__device__ __align__(128) unsigned char g_b1[256 * 3072];               // [256 n][1536 bf16] from W1l;W1r (transposed)
__device__ __align__(128) unsigned char g_b2[256 * 1536];               // [256 n][768 bf16]  from W2l|W2r (transposed)
__device__ __align__(128) float g_p[(size_t)NODES_PAD * 256];           // cols 0..127: h@W2l, 128..255: h@W2r
__device__ int   g_cnt [NODES];
__device__ float g_inv [NODES];
__device__ int   g_src [EDGES];
__device__ int   g_dst [EDGES];
__device__ int   g_off [NODES];
__device__ int   g_cur [NODES];
__device__ int   g_esrc[EDGES];
__device__ int   g_total;

// ---------------- PTX helpers ---------------------------------------------------
__device__ __forceinline__ uint32_t smem_u32(const void* p) {
    uint32_t a;
    asm("{ .reg .u64 t; cvta.to.shared.u64 t, %1; cvt.u32.u64 %0, t; }" : "=r"(a) : "l"(p));
    return a;
}
#define SW128(o) ((o) ^ (((o) >> 3) & 0x70))

__device__ __forceinline__ void cp16(uint32_t dst, const void* src) {
    asm volatile("cp.async.cg.shared.global [%0], [%1], 16;" :: "r"(dst), "l"(src));
}
#define CP_COMMIT() asm volatile("cp.async.commit_group;" ::: "memory")
#define CP_WAIT(n)  asm volatile("cp.async.wait_group %0;" :: "n"(n) : "memory")

__device__ __forceinline__ void ldsm4(uint32_t addr, uint32_t* r) {
    asm volatile("ldmatrix.sync.aligned.m8n8.x4.shared.b16 {%0,%1,%2,%3}, [%4];"
        : "=r"(r[0]), "=r"(r[1]), "=r"(r[2]), "=r"(r[3]) : "r"(addr));
}
__device__ __forceinline__ void mma16816(float* c, const uint32_t* a, uint32_t b0, uint32_t b1) {
    asm volatile("mma.sync.aligned.m16n8k16.row.col.f32.bf16.bf16.f32 "
        "{%0,%1,%2,%3}, {%4,%5,%6,%7}, {%8,%9}, {%0,%1,%2,%3};"
        : "+f"(c[0]), "+f"(c[1]), "+f"(c[2]), "+f"(c[3])
        : "r"(a[0]), "r"(a[1]), "r"(a[2]), "r"(a[3]), "r"(b0), "r"(b1));
}

// bf16 split helpers
__device__ __forceinline__ unsigned short f2bf(float v) {
    __nv_bfloat16 h = __float2bfloat16_rn(v);
    return *reinterpret_cast<unsigned short*>(&h);
}
__device__ __forceinline__ float bf2f(unsigned short u) {
    __nv_bfloat16 h = *reinterpret_cast<__nv_bfloat16*>(&u);
    return __bfloat162float(h);
}
__device__ __forceinline__ void bsplit(float v, unsigned short& hi, unsigned short& lo) {
    hi = f2bf(v);
    lo = f2bf(v - bf2f(hi));
}

// ---------------- init ----------------------------------------------------------
__global__ void k_init() {
    int i = blockIdx.x * blockDim.x + threadIdx.x;
    if (i < NODES) { g_cnt[i] = 0; g_cur[i] = 0; }
    if (i == 0) g_total = 0;
}

// ---------------- edge decode + degree count ------------------------------------
__global__ void k_edges(const void* __restrict__ ei_raw) {
    int e = blockIdx.x * blockDim.x + threadIdx.x;
    if (e >= EDGES) return;
    const int* w = (const int*)ei_raw;
    bool is64 = ((w[1] | w[3] | w[5] | w[7] | w[9] | w[11] | w[13] | w[15]) == 0);
    int s, d;
    if (is64) {
        const long long* e64 = (const long long*)ei_raw;
        s = (int)e64[e];
        d = (int)e64[EDGES + e];
    } else {
        s = w[e];
        d = w[EDGES + e];
    }
    g_src[e] = s;
    g_dst[e] = d;
    atomicAdd(&g_cnt[d], 1);
}

// ------- bucket allocation: per-block scan + one global atomic; also 1/deg -----
__global__ void k_alloc() {
    __shared__ int s[256];
    __shared__ int base;
    int t = threadIdx.x;
    int i = blockIdx.x * 256 + t;
    int v = (i < NODES) ? g_cnt[i] : 0;
    s[t] = v;
    __syncthreads();
#pragma unroll
    for (int d = 1; d < 256; d <<= 1) {
        int add = (t >= d) ? s[t - d] : 0;
        __syncthreads();
        s[t] += add;
        __syncthreads();
    }
    int incl = s[t];
    if (t == 255) base = atomicAdd(&g_total, incl);
    __syncthreads();
    if (i < NODES) {
        g_off[i] = base + incl - v;
        g_inv[i] = 1.f / fmaxf((float)v, 1.f);
    }
}

__global__ void k_fill() {
    int e = blockIdx.x * blockDim.x + threadIdx.x;
    if (e >= EDGES) return;
    int d = g_dst[e];
    int p = atomicAdd(&g_cur[d], 1);
    g_esrc[g_off[d] + p] = g_src[e];
}

// ------------- x -> bf16 triples into g_a1 cols [768..1536) ---------------------
__global__ void k_convx(const float* __restrict__ x) {
    int id = blockIdx.x * blockDim.x + threadIdx.x;
    if (id >= NODES * 64) return;
    int node = id >> 6;
    int j = id & 63;
    float4 v = *(const float4*)(x + (size_t)node * 256 + j * 4);
    unsigned short h0, l0, h1, l1, h2, l2, h3, l3;
    bsplit(v.x, h0, l0); bsplit(v.y, h1, l1);
    bsplit(v.z, h2, l2); bsplit(v.w, h3, l3);
    uint2* dst = (uint2*)(g_a1 + (size_t)node * 3072 + 1536 + j * 24);
    dst[0] = make_uint2((uint32_t)h0 | ((uint32_t)h0 << 16), (uint32_t)l0 | ((uint32_t)h1 << 16));
    dst[1] = make_uint2((uint32_t)h1 | ((uint32_t)l1 << 16), (uint32_t)h2 | ((uint32_t)h2 << 16));
    dst[2] = make_uint2((uint32_t)l2 | ((uint32_t)h3 << 16), (uint32_t)h3 | ((uint32_t)l3 << 16));
}

// ------------- weights -> transposed bf16 triples ([hi,lo,hi] pattern) ----------
__global__ void k_wprep(const float* __restrict__ W1l, const float* __restrict__ W1r,
                        const float* __restrict__ W2l, const float* __restrict__ W2r) {
    int id = blockIdx.x * blockDim.x + threadIdx.x;
    if (id < 256 * 512) {
        int n = id >> 9, k = id & 511;
        float w = (k < 256) ? W1l[k * 256 + n] : W1r[(k - 256) * 256 + n];
        unsigned short hi, lo;
        bsplit(w, hi, lo);
        unsigned short* d = (unsigned short*)(g_b1 + (size_t)n * 3072 + 6 * k);
        d[0] = hi; d[1] = lo; d[2] = hi;
    } else if (id < 256 * 512 + 256 * 256) {
        int id2 = id - 256 * 512;
        int n = id2 >> 8, k = id2 & 255;
        float w = (n < 128) ? W2l[k * 128 + n] : W2r[k * 128 + (n - 128)];
        unsigned short hi, lo;
        bsplit(w, hi, lo);
        unsigned short* d = (unsigned short*)(g_b2 + (size_t)n * 1536 + 6 * k);
        d[0] = hi; d[1] = lo; d[2] = hi;
    }
}

// ------------- layer-1 gather -> bf16 triples into g_a1 cols [0..768) -----------
// Two warps per node (128 cols each); 4-edge unroll for MLP.
__global__ void k_gather1(const float* __restrict__ x) {
    int gw   = (blockIdx.x * blockDim.x + threadIdx.x) >> 5;
    int node = gw >> 1;
    if (node >= NODES) return;
    int half = gw & 1;
    int lane = threadIdx.x & 31;
    int c = half * 128 + lane * 4;

    int e   = g_off[node];
    int end = e + g_cnt[node];
    float4 acc = make_float4(0.f, 0.f, 0.f, 0.f);
    for (; e + 3 < end; e += 4) {
        int s0 = g_esrc[e], s1 = g_esrc[e + 1], s2 = g_esrc[e + 2], s3 = g_esrc[e + 3];
        float4 v0 = *(const float4*)(x + (size_t)s0 * 256 + c);
        float4 v1 = *(const float4*)(x + (size_t)s1 * 256 + c);
        float4 v2 = *(const float4*)(x + (size_t)s2 * 256 + c);
        float4 v3 = *(const float4*)(x + (size_t)s3 * 256 + c);
        acc.x += (v0.x + v1.x) + (v2.x + v3.x);
        acc.y += (v0.y + v1.y) + (v2.y + v3.y);
        acc.z += (v0.z + v1.z) + (v2.z + v3.z);
        acc.w += (v0.w + v1.w) + (v2.w + v3.w);
    }
    for (; e < end; e++) {
        int s0 = g_esrc[e];
        float4 v0 = *(const float4*)(x + (size_t)s0 * 256 + c);
        acc.x += v0.x; acc.y += v0.y; acc.z += v0.z; acc.w += v0.w;
    }
    float inv = g_inv[node];
    acc.x *= inv; acc.y *= inv; acc.z *= inv; acc.w *= inv;
    unsigned short h0, l0, h1, l1, h2, l2, h3, l3;
    bsplit(acc.x, h0, l0); bsplit(acc.y, h1, l1);
    bsplit(acc.z, h2, l2); bsplit(acc.w, h3, l3);
    uint2* dst = (uint2*)(g_a1 + (size_t)node * 3072 + half * 768 + lane * 24);
    dst[0] = make_uint2((uint32_t)h0 | ((uint32_t)h0 << 16), (uint32_t)l0 | ((uint32_t)h1 << 16));
    dst[1] = make_uint2((uint32_t)h1 | ((uint32_t)l1 << 16), (uint32_t)h2 | ((uint32_t)h2 << 16));
    dst[2] = make_uint2((uint32_t)l2 | ((uint32_t)h3 << 16), (uint32_t)h3 | ((uint32_t)l3 << 16));
}

// ---------------- warp-MMA bf16 GEMM: D[128 rows, 128 cols] per CTA -------------
// MODE 1: A=g_a1 (K''=1536, 24 tiles), B=g_b1; epilogue bias+relu+split -> g_a2
// MODE 2: A=g_a2 (K''=768, 12 tiles),  B=g_b2; epilogue raw fp32 -> g_p
// 3-stage cp.async pipeline; SW128 smem; ldmatrix fragments; mma.m16n8k16.
// Grid (2, NTILES): the two column-half CTAs of one row tile are launch-adjacent
// so the second A-tile read hits L2 instead of DRAM.
#define STAGE_BYTES 32768                 // A 16KB + B 16KB
#define SMEM_DYN (3 * STAGE_BYTES)

template <int MODE>
__global__ __launch_bounds__(256, 2) void k_gemm(const float* __restrict__ bias) {
    constexpr int RB = (MODE == 1) ? 3072 : 1536;   // stream row bytes
    constexpr int KT = (MODE == 1) ? 24 : 12;       // 128-byte k-tiles (64 bf16)
    const unsigned char* gA = (MODE == 1) ? g_a1 : g_a2;
    const unsigned char* gB = (MODE == 1) ? g_b1 : g_b2;

    extern __shared__ __align__(128) unsigned char dsm[];
    const int t      = threadIdx.x;
    const int lane   = t & 31;
    const int wid    = t >> 5;
    const int warp_m = wid & 3;       // 4 M-groups of 32 rows
    const int warp_n = wid >> 2;      // 2 N-groups of 64 cols
    const int row0   = blockIdx.y * 128;
    const int col0   = blockIdx.x * 128;
    const uint32_t base = smem_u32(dsm);

    float c[2][8][4];
#pragma unroll
    for (int i = 0; i < 2; i++)
#pragma unroll
        for (int j = 0; j < 8; j++)
#pragma unroll
            for (int q = 0; q < 4; q++) c[i][j][q] = 0.f;

    // per-thread load slots: row r (0..127), 4 chunks of 16B at ch0
    const int lrow = t >> 1;
    const int ch0  = (t & 1) * 4;

    auto load_tile = [&](int kt, int s) {
        uint32_t sa = base + s * STAGE_BYTES;
        uint32_t sb = sa + 16384;
        const unsigned char* srcA = gA + (size_t)(row0 + lrow) * RB + (size_t)kt * 128 + ch0 * 16;
#pragma unroll
        for (int i = 0; i < 4; i++)
            cp16(sa + SW128(lrow * 128 + (ch0 + i) * 16), srcA + i * 16);
        const unsigned char* srcB = gB + (size_t)(col0 + lrow) * RB + (size_t)kt * 128 + ch0 * 16;
#pragma unroll
        for (int i = 0; i < 4; i++)
            cp16(sb + SW128(lrow * 128 + (ch0 + i) * 16), srcB + i * 16);
        CP_COMMIT();
    };

    const int lj = lane >> 3;     // 0..3 (ldmatrix sub-matrix)
    const int lr = lane & 7;

    auto compute = [&](int s) {
        uint32_t sa = base + s * STAGE_BYTES;
        uint32_t sb = sa + 16384;
#pragma unroll
        for (int ks = 0; ks < 4; ks++) {
            int cb = ks * 32 + (lj >> 1) * 16;
            uint32_t af[2][4];
#pragma unroll
            for (int mm = 0; mm < 2; mm++) {
                int row = warp_m * 32 + mm * 16 + (lj & 1) * 8 + lr;
                ldsm4(sa + SW128(row * 128 + cb), af[mm]);
            }
            uint32_t bf[4][4];
#pragma unroll
            for (int np = 0; np < 4; np++) {
                int row = warp_n * 64 + np * 16 + (lj & 1) * 8 + lr;
                ldsm4(sb + SW128(row * 128 + cb), bf[np]);
            }
#pragma unroll
            for (int mm = 0; mm < 2; mm++)
#pragma unroll
                for (int nn = 0; nn < 8; nn++)
                    mma16816(c[mm][nn], af[mm], bf[nn >> 1][nn & 1], bf[nn >> 1][(nn & 1) + 2]);
        }
    };

    load_tile(0, 0);
    load_tile(1, 1);
#pragma unroll 1
    for (int kt = 0; kt < KT; kt++) {
        CP_WAIT(1);
        __syncthreads();
        if (kt + 2 < KT) load_tile(kt + 2, (kt + 2) % 3);
        compute(kt % 3);
    }

    // ---------------- epilogue -------------------------------------------------
    const int qr = lane >> 2;
    const int qc = (lane & 3) * 2;
#pragma unroll
    for (int mm = 0; mm < 2; mm++) {
#pragma unroll
        for (int nn = 0; nn < 8; nn++) {
            int col = col0 + warp_n * 64 + nn * 8 + qc;
#pragma unroll
            for (int h = 0; h < 2; h++) {
                int row = row0 + warp_m * 32 + mm * 16 + qr + h * 8;
                float v0 = c[mm][nn][2 * h + 0];
                float v1 = c[mm][nn][2 * h + 1];
                if (MODE == 1) {
                    v0 = fmaxf(v0 + __ldg(&bias[col]), 0.f);
                    v1 = fmaxf(v1 + __ldg(&bias[col + 1]), 0.f);
                    unsigned short h0, l0, h1, l1;
                    bsplit(v0, h0, l0);
                    bsplit(v1, h1, l1);
                    uint32_t* d = (uint32_t*)(g_a2 + (size_t)row * 1536 + 6 * col);
                    d[0] = (uint32_t)h0 | ((uint32_t)h0 << 16);
                    d[1] = (uint32_t)l0 | ((uint32_t)h1 << 16);
                    d[2] = (uint32_t)h1 | ((uint32_t)l1 << 16);
                } else {
                    *(float2*)(g_p + (size_t)row * 256 + col) = make_float2(v0, v1);
                }
            }
        }
    }
}

// ---- layer-2 gather fused with epilogue: out = sigmoid(mean(p_l)+b2+p_r) ------
// One warp per node; 4-edge unroll for MLP.
__global__ void k_gather2_final(const float* __restrict__ b2,
                                float* __restrict__ out) {
    int node = (blockIdx.x * blockDim.x + threadIdx.x) >> 5;
    if (node >= NODES) return;
    int lane = threadIdx.x & 31;
    int c = lane * 4;

    int e   = g_off[node];
    int end = e + g_cnt[node];
    float4 acc = make_float4(0.f, 0.f, 0.f, 0.f);
    for (; e + 3 < end; e += 4) {
        int s0 = g_esrc[e], s1 = g_esrc[e + 1], s2 = g_esrc[e + 2], s3 = g_esrc[e + 3];
        float4 v0 = *(const float4*)(g_p + (size_t)s0 * 256 + c);
        float4 v1 = *(const float4*)(g_p + (size_t)s1 * 256 + c);
        float4 v2 = *(const float4*)(g_p + (size_t)s2 * 256 + c);
        float4 v3 = *(const float4*)(g_p + (size_t)s3 * 256 + c);
        acc.x += (v0.x + v1.x) + (v2.x + v3.x);
        acc.y += (v0.y + v1.y) + (v2.y + v3.y);
        acc.z += (v0.z + v1.z) + (v2.z + v3.z);
        acc.w += (v0.w + v1.w) + (v2.w + v3.w);
    }
    for (; e < end; e++) {
        int s0 = g_esrc[e];
        float4 v0 = *(const float4*)(g_p + (size_t)s0 * 256 + c);
        acc.x += v0.x; acc.y += v0.y; acc.z += v0.z; acc.w += v0.w;
    }
    float inv = g_inv[node];
    float4 bb = *(const float4*)(b2 + c);
    float4 rr = *(const float4*)(g_p + (size_t)node * 256 + 128 + c);
    float4 o;
    o.x = 1.f / (1.f + expf(-(acc.x * inv + bb.x + rr.x)));
    o.y = 1.f / (1.f + expf(-(acc.y * inv + bb.y + rr.y)));
    o.z = 1.f / (1.f + expf(-(acc.z * inv + bb.z + rr.z)));
    o.w = 1.f / (1.f + expf(-(acc.w * inv + bb.w + rr.w)));
    *(float4*)(out + (size_t)node * 128 + c) = o;
}

// ---------------- launch --------------------------------------------------------
extern "C" void kernel_launch(void* const* d_in, const int* in_sizes, int n_in,
                              void* d_out, int out_size) {
    (void)in_sizes; (void)n_in; (void)out_size;
    const float* x   = (const float*)d_in[0];
    const void*  ei  = d_in[1];
    const float* W1l = (const float*)d_in[2];
    const float* b1  = (const float*)d_in[3];
    const float* W1r = (const float*)d_in[4];
    const float* W2l = (const float*)d_in[5];
    const float* b2  = (const float*)d_in[6];
    const float* W2r = (const float*)d_in[7];
    float* out = (float*)d_out;

    cudaFuncSetAttribute(k_gemm<1>, cudaFuncAttributeMaxDynamicSharedMemorySize, SMEM_DYN);
    cudaFuncSetAttribute(k_gemm<2>, cudaFuncAttributeMaxDynamicSharedMemorySize, SMEM_DYN);

    k_init<<<(NODES + 255) / 256, 256>>>();
    k_edges<<<(EDGES + 255) / 256, 256>>>(ei);
    k_alloc<<<(NODES + 255) / 256, 256>>>();
    k_fill<<<(EDGES + 255) / 256, 256>>>();
    k_wprep<<<(256 * 512 + 256 * 256 + 255) / 256, 256>>>(W1l, W1r, W2l, W2r);
    k_convx<<<(NODES * 64 + 255) / 256, 256>>>(x);
    k_gather1<<<(NODES * 2 * 32 + 255) / 256, 256>>>(x);
    dim3 grid_g(2, NTILES);
    k_gemm<1><<<grid_g, 256, SMEM_DYN>>>(b1);
    k_gemm<2><<<grid_g, 256, SMEM_DYN>>>(b1 /*unused*/);
    k_gather2_final<<<(NODES * 32 + 255) / 256, 256>>>(b2, out);
}

// round 10
// speedup vs baseline: 1.4495x; 1.4495x over previous
#include <cuda_runtime.h>
#include <cuda_fp16.h>
#include <math.h>
#include <stdint.h>

#define NODES 50000
#define NODES_PAD 50048            // 391 tiles * 128
#define EDGES 800000
#define NTILES 391

// ---------------- scratch (static device globals; no allocs allowed) ----------
// 2-term FP16 split streams, pairwise interleave per original k:
//   A pattern: [hi, lo]   B pattern: [hi, hi]
//   plain GEMM over K''=2K yields hiA*hiB + loA*hiB = vA*hiB  (weights fp16-quantized)
__device__ __align__(128) unsigned char g_a1[(size_t)NODES_PAD * 2048]; // [N][1024 f16]: bytes [0,1024) agg, [1024,2048) x
__device__ __align__(128) unsigned char g_a2[(size_t)NODES_PAD * 1024]; // [N][512 f16] : h pairs
__device__ __align__(128) unsigned char g_b1[256 * 2048];               // [256 n][1024 f16] from W1l;W1r (transposed)
__device__ __align__(128) unsigned char g_b2[256 * 1024];               // [256 n][512 f16]  from W2l|W2r (transposed)
__device__ __align__(128) float g_p[(size_t)NODES_PAD * 256];           // cols 0..127: h@W2l, 128..255: h@W2r
__device__ int   g_cnt [NODES];
__device__ float g_inv [NODES];
__device__ int   g_src [EDGES];
__device__ int   g_dst [EDGES];
__device__ int   g_off [NODES];
__device__ int   g_cur [NODES];
__device__ int   g_esrc[EDGES];
__device__ int   g_total;

// ---------------- PTX helpers ---------------------------------------------------
__device__ __forceinline__ uint32_t smem_u32(const void* p) {
    uint32_t a;
    asm("{ .reg .u64 t; cvta.to.shared.u64 t, %1; cvt.u32.u64 %0, t; }" : "=r"(a) : "l"(p));
    return a;
}
#define SW128(o) ((o) ^ (((o) >> 3) & 0x70))

__device__ __forceinline__ void cp16(uint32_t dst, const void* src) {
    asm volatile("cp.async.cg.shared.global [%0], [%1], 16;" :: "r"(dst), "l"(src));
}
#define CP_COMMIT() asm volatile("cp.async.commit_group;" ::: "memory")
#define CP_WAIT(n)  asm volatile("cp.async.wait_group %0;" :: "n"(n) : "memory")

__device__ __forceinline__ void ldsm4(uint32_t addr, uint32_t* r) {
    asm volatile("ldmatrix.sync.aligned.m8n8.x4.shared.b16 {%0,%1,%2,%3}, [%4];"
        : "=r"(r[0]), "=r"(r[1]), "=r"(r[2]), "=r"(r[3]) : "r"(addr));
}
__device__ __forceinline__ void mma16816(float* c, const uint32_t* a, uint32_t b0, uint32_t b1) {
    asm volatile("mma.sync.aligned.m16n8k16.row.col.f32.f16.f16.f32 "
        "{%0,%1,%2,%3}, {%4,%5,%6,%7}, {%8,%9}, {%0,%1,%2,%3};"
        : "+f"(c[0]), "+f"(c[1]), "+f"(c[2]), "+f"(c[3])
        : "r"(a[0]), "r"(a[1]), "r"(a[2]), "r"(a[3]), "r"(b0), "r"(b1));
}

// fp16 split helpers
__device__ __forceinline__ unsigned short f2h(float v) {
    __half h = __float2half_rn(v);
    return *reinterpret_cast<unsigned short*>(&h);
}
__device__ __forceinline__ float h2f(unsigned short u) {
    __half h = *reinterpret_cast<__half*>(&u);
    return __half2float(h);
}
// v -> (hi, lo) both fp16, hi = rn(v), lo = rn(v - hi)
__device__ __forceinline__ uint32_t hpack(float v) {
    unsigned short hi = f2h(v);
    unsigned short lo = f2h(v - h2f(hi));
    return (uint32_t)hi | ((uint32_t)lo << 16);
}

// ---------------- init ----------------------------------------------------------
__global__ void k_init() {
    int i = blockIdx.x * blockDim.x + threadIdx.x;
    if (i < NODES) { g_cnt[i] = 0; g_cur[i] = 0; }
    if (i == 0) g_total = 0;
}

// ---------------- edge decode + degree count ------------------------------------
__global__ void k_edges(const void* __restrict__ ei_raw) {
    int e = blockIdx.x * blockDim.x + threadIdx.x;
    if (e >= EDGES) return;
    const int* w = (const int*)ei_raw;
    bool is64 = ((w[1] | w[3] | w[5] | w[7] | w[9] | w[11] | w[13] | w[15]) == 0);
    int s, d;
    if (is64) {
        const long long* e64 = (const long long*)ei_raw;
        s = (int)e64[e];
        d = (int)e64[EDGES + e];
    } else {
        s = w[e];
        d = w[EDGES + e];
    }
    g_src[e] = s;
    g_dst[e] = d;
    atomicAdd(&g_cnt[d], 1);
}

// ------- bucket allocation: per-block scan + one global atomic; also 1/deg -----
__global__ void k_alloc() {
    __shared__ int s[256];
    __shared__ int base;
    int t = threadIdx.x;
    int i = blockIdx.x * 256 + t;
    int v = (i < NODES) ? g_cnt[i] : 0;
    s[t] = v;
    __syncthreads();
#pragma unroll
    for (int d = 1; d < 256; d <<= 1) {
        int add = (t >= d) ? s[t - d] : 0;
        __syncthreads();
        s[t] += add;
        __syncthreads();
    }
    int incl = s[t];
    if (t == 255) base = atomicAdd(&g_total, incl);
    __syncthreads();
    if (i < NODES) {
        g_off[i] = base + incl - v;
        g_inv[i] = 1.f / fmaxf((float)v, 1.f);
    }
}

__global__ void k_fill() {
    int e = blockIdx.x * blockDim.x + threadIdx.x;
    if (e >= EDGES) return;
    int d = g_dst[e];
    int p = atomicAdd(&g_cur[d], 1);
    g_esrc[g_off[d] + p] = g_src[e];
}

// ------------- weights -> transposed fp16 [hi,hi] streams -----------------------
__global__ void k_wprep(const float* __restrict__ W1l, const float* __restrict__ W1r,
                        const float* __restrict__ W2l, const float* __restrict__ W2r) {
    int id = blockIdx.x * blockDim.x + threadIdx.x;
    if (id < 256 * 512) {
        int n = id >> 9, k = id & 511;
        float w = (k < 256) ? W1l[k * 256 + n] : W1r[(k - 256) * 256 + n];
        uint32_t hi = f2h(w);
        *(uint32_t*)(g_b1 + (size_t)n * 2048 + 4 * k) = hi | (hi << 16);
    } else if (id < 256 * 512 + 256 * 256) {
        int id2 = id - 256 * 512;
        int n = id2 >> 8, k = id2 & 255;
        float w = (n < 128) ? W2l[k * 128 + n] : W2r[k * 128 + (n - 128)];
        uint32_t hi = f2h(w);
        *(uint32_t*)(g_b2 + (size_t)n * 1024 + 4 * k) = hi | (hi << 16);
    }
}

// ------------- layer-1 gather -> fp16 pairs; also converts own x row -------------
// Two warps per node (128 cols each); lane owns 4 cols.
__global__ void k_gather1(const float* __restrict__ x) {
    int gw   = (blockIdx.x * blockDim.x + threadIdx.x) >> 5;
    int node = gw >> 1;
    if (node >= NODES) return;
    int half = gw & 1;
    int lane = threadIdx.x & 31;
    int c = half * 128 + lane * 4;

    int e   = g_off[node];
    int end = e + g_cnt[node];
    float4 acc = make_float4(0.f, 0.f, 0.f, 0.f);
    for (; e + 3 < end; e += 4) {
        int s0 = g_esrc[e], s1 = g_esrc[e + 1], s2 = g_esrc[e + 2], s3 = g_esrc[e + 3];
        float4 v0 = *(const float4*)(x + (size_t)s0 * 256 + c);
        float4 v1 = *(const float4*)(x + (size_t)s1 * 256 + c);
        float4 v2 = *(const float4*)(x + (size_t)s2 * 256 + c);
        float4 v3 = *(const float4*)(x + (size_t)s3 * 256 + c);
        acc.x += (v0.x + v1.x) + (v2.x + v3.x);
        acc.y += (v0.y + v1.y) + (v2.y + v3.y);
        acc.z += (v0.z + v1.z) + (v2.z + v3.z);
        acc.w += (v0.w + v1.w) + (v2.w + v3.w);
    }
    for (; e < end; e++) {
        int s0 = g_esrc[e];
        float4 v0 = *(const float4*)(x + (size_t)s0 * 256 + c);
        acc.x += v0.x; acc.y += v0.y; acc.z += v0.z; acc.w += v0.w;
    }
    float inv = g_inv[node];
    // agg part: byte offset 4*c in [0,1024)
    uint4 pa;
    pa.x = hpack(acc.x * inv);
    pa.y = hpack(acc.y * inv);
    pa.z = hpack(acc.z * inv);
    pa.w = hpack(acc.w * inv);
    *(uint4*)(g_a1 + (size_t)node * 2048 + 4 * c) = pa;
    // own x row conversion (fused former k_convx): byte offset 1024 + 4*c
    float4 xv = *(const float4*)(x + (size_t)node * 256 + c);
    uint4 px;
    px.x = hpack(xv.x);
    px.y = hpack(xv.y);
    px.z = hpack(xv.z);
    px.w = hpack(xv.w);
    *(uint4*)(g_a1 + (size_t)node * 2048 + 1024 + 4 * c) = px;
}

// ---------------- warp-MMA fp16 GEMM: D[128 rows, 128 cols] per CTA -------------
// MODE 1: A=g_a1 (K''=1024, 16 tiles), B=g_b1; epilogue bias+relu+split -> g_a2
// MODE 2: A=g_a2 (K''=512,  8 tiles),  B=g_b2; epilogue raw fp32 -> g_p
// 3-stage cp.async pipeline; SW128 smem; ldmatrix fragments; mma.m16n8k16.
#define STAGE_BYTES 32768                 // A 16KB + B 16KB
#define SMEM_DYN (3 * STAGE_BYTES)

template <int MODE>
__global__ __launch_bounds__(256, 2) void k_gemm(const float* __restrict__ bias) {
    constexpr int RB = (MODE == 1) ? 2048 : 1024;   // stream row bytes
    constexpr int KT = (MODE == 1) ? 16 : 8;        // 128-byte k-tiles (64 f16)
    const unsigned char* gA = (MODE == 1) ? g_a1 : g_a2;
    const unsigned char* gB = (MODE == 1) ? g_b1 : g_b2;

    extern __shared__ __align__(128) unsigned char dsm[];
    const int t      = threadIdx.x;
    const int lane   = t & 31;
    const int wid    = t >> 5;
    const int warp_m = wid & 3;       // 4 M-groups of 32 rows
    const int warp_n = wid >> 2;      // 2 N-groups of 64 cols
    const int row0   = blockIdx.y * 128;
    const int col0   = blockIdx.x * 128;
    const uint32_t base = smem_u32(dsm);

    float c[2][8][4];
#pragma unroll
    for (int i = 0; i < 2; i++)
#pragma unroll
        for (int j = 0; j < 8; j++)
#pragma unroll
            for (int q = 0; q < 4; q++) c[i][j][q] = 0.f;

    // per-thread load slots: row r (0..127), 4 chunks of 16B at ch0
    const int lrow = t >> 1;
    const int ch0  = (t & 1) * 4;

    auto load_tile = [&](int kt, int s) {
        uint32_t sa = base + s * STAGE_BYTES;
        uint32_t sb = sa + 16384;
        const unsigned char* srcA = gA + (size_t)(row0 + lrow) * RB + (size_t)kt * 128 + ch0 * 16;
#pragma unroll
        for (int i = 0; i < 4; i++)
            cp16(sa + SW128(lrow * 128 + (ch0 + i) * 16), srcA + i * 16);
        const unsigned char* srcB = gB + (size_t)(col0 + lrow) * RB + (size_t)kt * 128 + ch0 * 16;
#pragma unroll
        for (int i = 0; i < 4; i++)
            cp16(sb + SW128(lrow * 128 + (ch0 + i) * 16), srcB + i * 16);
        CP_COMMIT();
    };

    const int lj = lane >> 3;     // 0..3 (ldmatrix sub-matrix)
    const int lr = lane & 7;

    auto compute = [&](int s) {
        uint32_t sa = base + s * STAGE_BYTES;
        uint32_t sb = sa + 16384;
#pragma unroll
        for (int ks = 0; ks < 4; ks++) {
            int cb = ks * 32 + (lj >> 1) * 16;
            uint32_t af[2][4];
#pragma unroll
            for (int mm = 0; mm < 2; mm++) {
                int row = warp_m * 32 + mm * 16 + (lj & 1) * 8 + lr;
                ldsm4(sa + SW128(row * 128 + cb), af[mm]);
            }
            uint32_t bf[4][4];
#pragma unroll
            for (int np = 0; np < 4; np++) {
                int row = warp_n * 64 + np * 16 + (lj & 1) * 8 + lr;
                ldsm4(sb + SW128(row * 128 + cb), bf[np]);
            }
#pragma unroll
            for (int mm = 0; mm < 2; mm++)
#pragma unroll
                for (int nn = 0; nn < 8; nn++)
                    mma16816(c[mm][nn], af[mm], bf[nn >> 1][nn & 1], bf[nn >> 1][(nn & 1) + 2]);
        }
    };

    load_tile(0, 0);
    load_tile(1, 1);
#pragma unroll 1
    for (int kt = 0; kt < KT; kt++) {
        CP_WAIT(1);
        __syncthreads();
        if (kt + 2 < KT) load_tile(kt + 2, (kt + 2) % 3);
        compute(kt % 3);
    }

    // ---------------- epilogue -------------------------------------------------
    const int qr = lane >> 2;
    const int qc = (lane & 3) * 2;
#pragma unroll
    for (int mm = 0; mm < 2; mm++) {
#pragma unroll
        for (int nn = 0; nn < 8; nn++) {
            int col = col0 + warp_n * 64 + nn * 8 + qc;
#pragma unroll
            for (int h = 0; h < 2; h++) {
                int row = row0 + warp_m * 32 + mm * 16 + qr + h * 8;
                float v0 = c[mm][nn][2 * h + 0];
                float v1 = c[mm][nn][2 * h + 1];
                if (MODE == 1) {
                    v0 = fmaxf(v0 + __ldg(&bias[col]), 0.f);
                    v1 = fmaxf(v1 + __ldg(&bias[col + 1]), 0.f);
                    uint2* d = (uint2*)(g_a2 + (size_t)row * 1024 + 4 * col);
                    *d = make_uint2(hpack(v0), hpack(v1));
                } else {
                    *(float2*)(g_p + (size_t)row * 256 + col) = make_float2(v0, v1);
                }
            }
        }
    }
}

// ---- layer-2 gather fused with epilogue: out = sigmoid(mean(p_l)+b2+p_r) ------
// One warp per node; 4-edge unroll for MLP.
__global__ void k_gather2_final(const float* __restrict__ b2,
                                float* __restrict__ out) {
    int node = (blockIdx.x * blockDim.x + threadIdx.x) >> 5;
    if (node >= NODES) return;
    int lane = threadIdx.x & 31;
    int c = lane * 4;

    int e   = g_off[node];
    int end = e + g_cnt[node];
    float4 acc = make_float4(0.f, 0.f, 0.f, 0.f);
    for (; e + 3 < end; e += 4) {
        int s0 = g_esrc[e], s1 = g_esrc[e + 1], s2 = g_esrc[e + 2], s3 = g_esrc[e + 3];
        float4 v0 = *(const float4*)(g_p + (size_t)s0 * 256 + c);
        float4 v1 = *(const float4*)(g_p + (size_t)s1 * 256 + c);
        float4 v2 = *(const float4*)(g_p + (size_t)s2 * 256 + c);
        float4 v3 = *(const float4*)(g_p + (size_t)s3 * 256 + c);
        acc.x += (v0.x + v1.x) + (v2.x + v3.x);
        acc.y += (v0.y + v1.y) + (v2.y + v3.y);
        acc.z += (v0.z + v1.z) + (v2.z + v3.z);
        acc.w += (v0.w + v1.w) + (v2.w + v3.w);
    }
    for (; e < end; e++) {
        int s0 = g_esrc[e];
        float4 v0 = *(const float4*)(g_p + (size_t)s0 * 256 + c);
        acc.x += v0.x; acc.y += v0.y; acc.z += v0.z; acc.w += v0.w;
    }
    float inv = g_inv[node];
    float4 bb = *(const float4*)(b2 + c);
    float4 rr = *(const float4*)(g_p + (size_t)node * 256 + 128 + c);
    float4 o;
    o.x = 1.f / (1.f + expf(-(acc.x * inv + bb.x + rr.x)));
    o.y = 1.f / (1.f + expf(-(acc.y * inv + bb.y + rr.y)));
    o.z = 1.f / (1.f + expf(-(acc.z * inv + bb.z + rr.z)));
    o.w = 1.f / (1.f + expf(-(acc.w * inv + bb.w + rr.w)));
    *(float4*)(out + (size_t)node * 128 + c) = o;
}

// ---------------- launch --------------------------------------------------------
extern "C" void kernel_launch(void* const* d_in, const int* in_sizes, int n_in,
                              void* d_out, int out_size) {
    (void)in_sizes; (void)n_in; (void)out_size;
    const float* x   = (const float*)d_in[0];
    const void*  ei  = d_in[1];
    const float* W1l = (const float*)d_in[2];
    const float* b1  = (const float*)d_in[3];
    const float* W1r = (const float*)d_in[4];
    const float* W2l = (const float*)d_in[5];
    const float* b2  = (const float*)d_in[6];
    const float* W2r = (const float*)d_in[7];
    float* out = (float*)d_out;

    cudaFuncSetAttribute(k_gemm<1>, cudaFuncAttributeMaxDynamicSharedMemorySize, SMEM_DYN);
    cudaFuncSetAttribute(k_gemm<2>, cudaFuncAttributeMaxDynamicSharedMemorySize, SMEM_DYN);

    k_init<<<(NODES + 255) / 256, 256>>>();
    k_edges<<<(EDGES + 255) / 256, 256>>>(ei);
    k_alloc<<<(NODES + 255) / 256, 256>>>();
    k_fill<<<(EDGES + 255) / 256, 256>>>();
    k_wprep<<<(256 * 512 + 256 * 256 + 255) / 256, 256>>>(W1l, W1r, W2l, W2r);
    k_gather1<<<(NODES * 2 * 32 + 255) / 256, 256>>>(x);
    dim3 grid_g(2, NTILES);
    k_gemm<1><<<grid_g, 256, SMEM_DYN>>>(b1);
    k_gemm<2><<<grid_g, 256, SMEM_DYN>>>(b1 /*unused*/);
    k_gather2_final<<<(NODES * 32 + 255) / 256, 256>>>(b2, out);
}

// round 12
// speedup vs baseline: 2.1581x; 1.4889x over previous
#include <cuda_runtime.h>
#include <cuda_fp16.h>
#include <math.h>
#include <stdint.h>

#define NODES 50000
#define NODES_PAD 50048            // 391 tiles * 128
#define EDGES 800000
#define NTILES 391

// ---------------- scratch (static device globals; no allocs allowed) ----------
// Pure fp16 pipeline: activations and weights quantized to fp16, fp32 accum.
__device__ __align__(128) unsigned char g_a1[(size_t)NODES_PAD * 1024]; // [N][512 f16]: [0,512)B agg, [512,1024)B x
__device__ __align__(128) unsigned char g_a2[(size_t)NODES_PAD * 512];  // [N][256 f16]: h
__device__ __align__(128) unsigned char g_b1[256 * 1024];               // [256 n][512 f16]: W1l;W1r transposed
__device__ __align__(128) unsigned char g_b2[256 * 512];                // [256 n][256 f16]: W2l|W2r transposed
__device__ __align__(128) unsigned char g_pl[(size_t)NODES_PAD * 256];  // [N][128 f16]: h@W2l (gathered later)
__device__ __align__(128) float g_pr[(size_t)NODES_PAD * 128];          // [N][128 f32]: h@W2r (self term)
__device__ int   g_cnt [NODES];
__device__ float g_inv [NODES];
__device__ int   g_src [EDGES];
__device__ int   g_dst [EDGES];
__device__ int   g_off [NODES];
__device__ int   g_cur [NODES];
__device__ int   g_esrc[EDGES];
__device__ int   g_total;

// ---------------- PTX helpers ---------------------------------------------------
__device__ __forceinline__ uint32_t smem_u32(const void* p) {
    uint32_t a;
    asm("{ .reg .u64 t; cvta.to.shared.u64 t, %1; cvt.u32.u64 %0, t; }" : "=r"(a) : "l"(p));
    return a;
}
#define SW128(o) ((o) ^ (((o) >> 3) & 0x70))

__device__ __forceinline__ void cp16(uint32_t dst, const void* src) {
    asm volatile("cp.async.cg.shared.global [%0], [%1], 16;" :: "r"(dst), "l"(src));
}
#define CP_COMMIT() asm volatile("cp.async.commit_group;" ::: "memory")
#define CP_WAIT(n)  asm volatile("cp.async.wait_group %0;" :: "n"(n) : "memory")

__device__ __forceinline__ void ldsm4(uint32_t addr, uint32_t* r) {
    asm volatile("ldmatrix.sync.aligned.m8n8.x4.shared.b16 {%0,%1,%2,%3}, [%4];"
        : "=r"(r[0]), "=r"(r[1]), "=r"(r[2]), "=r"(r[3]) : "r"(addr));
}
__device__ __forceinline__ void mma16816(float* c, const uint32_t* a, uint32_t b0, uint32_t b1) {
    asm volatile("mma.sync.aligned.m16n8k16.row.col.f32.f16.f16.f32 "
        "{%0,%1,%2,%3}, {%4,%5,%6,%7}, {%8,%9}, {%0,%1,%2,%3};"
        : "+f"(c[0]), "+f"(c[1]), "+f"(c[2]), "+f"(c[3])
        : "r"(a[0]), "r"(a[1]), "r"(a[2]), "r"(a[3]), "r"(b0), "r"(b1));
}

__device__ __forceinline__ unsigned short f2h(float v) {
    __half h = __float2half_rn(v);
    return *reinterpret_cast<unsigned short*>(&h);
}
__device__ __forceinline__ uint32_t pack2h(float a, float b) {
    return (uint32_t)f2h(a) | ((uint32_t)f2h(b) << 16);
}
__device__ __forceinline__ float2 uph(uint32_t w) {
    return __half22float2(*reinterpret_cast<__half2*>(&w));
}

// ---------------- init ----------------------------------------------------------
__global__ void k_init() {
    int i = blockIdx.x * blockDim.x + threadIdx.x;
    if (i < NODES) { g_cnt[i] = 0; g_cur[i] = 0; }
    if (i == 0) g_total = 0;
}

// ---------------- edge decode + degree count ------------------------------------
__global__ void k_edges(const void* __restrict__ ei_raw) {
    int e = blockIdx.x * blockDim.x + threadIdx.x;
    if (e >= EDGES) return;
    const int* w = (const int*)ei_raw;
    bool is64 = ((w[1] | w[3] | w[5] | w[7] | w[9] | w[11] | w[13] | w[15]) == 0);
    int s, d;
    if (is64) {
        const long long* e64 = (const long long*)ei_raw;
        s = (int)e64[e];
        d = (int)e64[EDGES + e];
    } else {
        s = w[e];
        d = w[EDGES + e];
    }
    g_src[e] = s;
    g_dst[e] = d;
    atomicAdd(&g_cnt[d], 1);
}

// ------- bucket allocation: per-block scan + one global atomic; also 1/deg -----
__global__ void k_alloc() {
    __shared__ int s[256];
    __shared__ int base;
    int t = threadIdx.x;
    int i = blockIdx.x * 256 + t;
    int v = (i < NODES) ? g_cnt[i] : 0;
    s[t] = v;
    __syncthreads();
#pragma unroll
    for (int d = 1; d < 256; d <<= 1) {
        int add = (t >= d) ? s[t - d] : 0;
        __syncthreads();
        s[t] += add;
        __syncthreads();
    }
    int incl = s[t];
    if (t == 255) base = atomicAdd(&g_total, incl);
    __syncthreads();
    if (i < NODES) {
        g_off[i] = base + incl - v;
        g_inv[i] = 1.f / fmaxf((float)v, 1.f);
    }
}

__global__ void k_fill() {
    int e = blockIdx.x * blockDim.x + threadIdx.x;
    if (e >= EDGES) return;
    int d = g_dst[e];
    int p = atomicAdd(&g_cur[d], 1);
    g_esrc[g_off[d] + p] = g_src[e];
}

// ------------- x fp32 -> fp16 into g_a1 self-half --------------------------------
__global__ void k_convh(const float* __restrict__ x) {
    int id = blockIdx.x * blockDim.x + threadIdx.x;
    if (id >= NODES * 32) return;
    int node = id >> 5;
    int col  = (id & 31) * 8;
    const float4* src = (const float4*)(x + (size_t)node * 256 + col);
    float4 a = src[0], b = src[1];
    uint4 o;
    o.x = pack2h(a.x, a.y);
    o.y = pack2h(a.z, a.w);
    o.z = pack2h(b.x, b.y);
    o.w = pack2h(b.z, b.w);
    *(uint4*)(g_a1 + (size_t)node * 1024 + 512 + col * 2) = o;
}

// ------------- weights -> transposed fp16 streams --------------------------------
__global__ void k_wprep(const float* __restrict__ W1l, const float* __restrict__ W1r,
                        const float* __restrict__ W2l, const float* __restrict__ W2r) {
    int id = blockIdx.x * blockDim.x + threadIdx.x;
    if (id < 256 * 512) {
        int n = id >> 9, k = id & 511;
        float w = (k < 256) ? W1l[k * 256 + n] : W1r[(k - 256) * 256 + n];
        *(unsigned short*)(g_b1 + (size_t)n * 1024 + 2 * k) = f2h(w);
    } else if (id < 256 * 512 + 256 * 256) {
        int id2 = id - 256 * 512;
        int n = id2 >> 8, k = id2 & 255;
        float w = (n < 128) ? W2l[k * 128 + n] : W2r[k * 128 + (n - 128)];
        *(unsigned short*)(g_b2 + (size_t)n * 512 + 2 * k) = f2h(w);
    }
}

// ------------- layer-1 gather (fp16 rows, fp32 accumulate) -----------------------
// One warp per node; lane owns 8 cols (16 bytes of fp16).
__global__ void k_gather1() {
    int node = (blockIdx.x * blockDim.x + threadIdx.x) >> 5;
    if (node >= NODES) return;
    int lane = threadIdx.x & 31;
    int boff = lane * 16;          // byte offset within the 512-byte fp16 half-row

    int e   = g_off[node];
    int end = e + g_cnt[node];
    float acc[8];
#pragma unroll
    for (int i = 0; i < 8; i++) acc[i] = 0.f;

    for (; e + 1 < end; e += 2) {
        int s0 = g_esrc[e], s1 = g_esrc[e + 1];
        uint4 v0 = *(const uint4*)(g_a1 + (size_t)s0 * 1024 + 512 + boff);
        uint4 v1 = *(const uint4*)(g_a1 + (size_t)s1 * 1024 + 512 + boff);
        float2 f;
        f = uph(v0.x); acc[0] += f.x; acc[1] += f.y;
        f = uph(v0.y); acc[2] += f.x; acc[3] += f.y;
        f = uph(v0.z); acc[4] += f.x; acc[5] += f.y;
        f = uph(v0.w); acc[6] += f.x; acc[7] += f.y;
        f = uph(v1.x); acc[0] += f.x; acc[1] += f.y;
        f = uph(v1.y); acc[2] += f.x; acc[3] += f.y;
        f = uph(v1.z); acc[4] += f.x; acc[5] += f.y;
        f = uph(v1.w); acc[6] += f.x; acc[7] += f.y;
    }
    if (e < end) {
        int s0 = g_esrc[e];
        uint4 v0 = *(const uint4*)(g_a1 + (size_t)s0 * 1024 + 512 + boff);
        float2 f;
        f = uph(v0.x); acc[0] += f.x; acc[1] += f.y;
        f = uph(v0.y); acc[2] += f.x; acc[3] += f.y;
        f = uph(v0.z); acc[4] += f.x; acc[5] += f.y;
        f = uph(v0.w); acc[6] += f.x; acc[7] += f.y;
    }
    float inv = g_inv[node];
    uint4 o;
    o.x = pack2h(acc[0] * inv, acc[1] * inv);
    o.y = pack2h(acc[2] * inv, acc[3] * inv);
    o.z = pack2h(acc[4] * inv, acc[5] * inv);
    o.w = pack2h(acc[6] * inv, acc[7] * inv);
    *(uint4*)(g_a1 + (size_t)node * 1024 + boff) = o;
}

// ---------------- warp-MMA fp16 GEMM: D[128 rows, 128 cols] per CTA --------------
// MODE 1: A=g_a1 (K=512, 8 tiles), B=g_b1; epilogue bias+relu -> g_a2 fp16
// MODE 2: A=g_a2 (K=256, 4 tiles), B=g_b2; epilogue: left->g_pl fp16, right->g_pr f32
#define STAGE_BYTES 32768                 // A 16KB + B 16KB
#define SMEM_DYN (3 * STAGE_BYTES)

template <int MODE>
__global__ __launch_bounds__(256, 2) void k_gemm(const float* __restrict__ bias) {
    constexpr int RB = (MODE == 1) ? 1024 : 512;    // stream row bytes
    constexpr int KT = (MODE == 1) ? 8 : 4;         // 128-byte k-tiles (64 f16)
    const unsigned char* gA = (MODE == 1) ? g_a1 : g_a2;
    const unsigned char* gB = (MODE == 1) ? g_b1 : g_b2;

    extern __shared__ __align__(128) unsigned char dsm[];
    const int t      = threadIdx.x;
    const int lane   = t & 31;
    const int wid    = t >> 5;
    const int warp_m = wid & 3;       // 4 M-groups of 32 rows
    const int warp_n = wid >> 2;      // 2 N-groups of 64 cols
    const int row0   = blockIdx.y * 128;
    const int col0   = blockIdx.x * 128;
    const uint32_t base = smem_u32(dsm);

    float c[2][8][4];
#pragma unroll
    for (int i = 0; i < 2; i++)
#pragma unroll
        for (int j = 0; j < 8; j++)
#pragma unroll
            for (int q = 0; q < 4; q++) c[i][j][q] = 0.f;

    const int lrow = t >> 1;
    const int ch0  = (t & 1) * 4;

    auto load_tile = [&](int kt, int s) {
        uint32_t sa = base + s * STAGE_BYTES;
        uint32_t sb = sa + 16384;
        const unsigned char* srcA = gA + (size_t)(row0 + lrow) * RB + (size_t)kt * 128 + ch0 * 16;
#pragma unroll
        for (int i = 0; i < 4; i++)
            cp16(sa + SW128(lrow * 128 + (ch0 + i) * 16), srcA + i * 16);
        const unsigned char* srcB = gB + (size_t)(col0 + lrow) * RB + (size_t)kt * 128 + ch0 * 16;
#pragma unroll
        for (int i = 0; i < 4; i++)
            cp16(sb + SW128(lrow * 128 + (ch0 + i) * 16), srcB + i * 16);
        CP_COMMIT();
    };

    const int lj = lane >> 3;
    const int lr = lane & 7;

    auto compute = [&](int s) {
        uint32_t sa = base + s * STAGE_BYTES;
        uint32_t sb = sa + 16384;
#pragma unroll
        for (int ks = 0; ks < 4; ks++) {
            int cb = ks * 32 + (lj >> 1) * 16;
            uint32_t af[2][4];
#pragma unroll
            for (int mm = 0; mm < 2; mm++) {
                int row = warp_m * 32 + mm * 16 + (lj & 1) * 8 + lr;
                ldsm4(sa + SW128(row * 128 + cb), af[mm]);
            }
            uint32_t bf[4][4];
#pragma unroll
            for (int np = 0; np < 4; np++) {
                int row = warp_n * 64 + np * 16 + (lj & 1) * 8 + lr;
                ldsm4(sb + SW128(row * 128 + cb), bf[np]);
            }
#pragma unroll
            for (int mm = 0; mm < 2; mm++)
#pragma unroll
                for (int nn = 0; nn < 8; nn++)
                    mma16816(c[mm][nn], af[mm], bf[nn >> 1][nn & 1], bf[nn >> 1][(nn & 1) + 2]);
        }
    };

    load_tile(0, 0);
    load_tile(1, 1);
#pragma unroll 1
    for (int kt = 0; kt < KT; kt++) {
        if (kt == KT - 1) { CP_WAIT(0); } else { CP_WAIT(1); }
        __syncthreads();
        if (kt + 2 < KT) load_tile(kt + 2, (kt + 2) % 3);
        compute(kt % 3);
    }

    // ---------------- epilogue -------------------------------------------------
    const int qr = lane >> 2;
    const int qc = (lane & 3) * 2;
#pragma unroll
    for (int mm = 0; mm < 2; mm++) {
#pragma unroll
        for (int nn = 0; nn < 8; nn++) {
            int col = col0 + warp_n * 64 + nn * 8 + qc;
#pragma unroll
            for (int h = 0; h < 2; h++) {
                int row = row0 + warp_m * 32 + mm * 16 + qr + h * 8;
                float v0 = c[mm][nn][2 * h + 0];
                float v1 = c[mm][nn][2 * h + 1];
                if (MODE == 1) {
                    v0 = fmaxf(v0 + __ldg(&bias[col]), 0.f);
                    v1 = fmaxf(v1 + __ldg(&bias[col + 1]), 0.f);
                    *(uint32_t*)(g_a2 + (size_t)row * 512 + 2 * col) = pack2h(v0, v1);
                } else {
                    if (col < 128) {
                        *(uint32_t*)(g_pl + (size_t)row * 256 + 2 * col) = pack2h(v0, v1);
                    } else {
                        *(float2*)(g_pr + (size_t)row * 128 + (col - 128)) = make_float2(v0, v1);
                    }
                }
            }
        }
    }
}

// ---- layer-2 gather fused with epilogue: out = sigmoid(mean(p_l)+b2+p_r) -------
// One warp per node; lane owns 4 cols (8 bytes fp16 per neighbor row).
__global__ void k_gather2_final(const float* __restrict__ b2,
                                float* __restrict__ out) {
    int node = (blockIdx.x * blockDim.x + threadIdx.x) >> 5;
    if (node >= NODES) return;
    int lane = threadIdx.x & 31;
    int c = lane * 4;

    int e   = g_off[node];
    int end = e + g_cnt[node];
    float4 acc = make_float4(0.f, 0.f, 0.f, 0.f);
    for (; e + 1 < end; e += 2) {
        int s0 = g_esrc[e], s1 = g_esrc[e + 1];
        uint2 v0 = *(const uint2*)(g_pl + (size_t)s0 * 256 + 2 * c);
        uint2 v1 = *(const uint2*)(g_pl + (size_t)s1 * 256 + 2 * c);
        float2 f;
        f = uph(v0.x); acc.x += f.x; acc.y += f.y;
        f = uph(v0.y); acc.z += f.x; acc.w += f.y;
        f = uph(v1.x); acc.x += f.x; acc.y += f.y;
        f = uph(v1.y); acc.z += f.x; acc.w += f.y;
    }
    if (e < end) {
        int s0 = g_esrc[e];
        uint2 v0 = *(const uint2*)(g_pl + (size_t)s0 * 256 + 2 * c);
        float2 f;
        f = uph(v0.x); acc.x += f.x; acc.y += f.y;
        f = uph(v0.y); acc.z += f.x; acc.w += f.y;
    }
    float inv = g_inv[node];
    float4 bb = *(const float4*)(b2 + c);
    float4 rr = *(const float4*)(g_pr + (size_t)node * 128 + c);
    float4 o;
    o.x = 1.f / (1.f + expf(-(acc.x * inv + bb.x + rr.x)));
    o.y = 1.f / (1.f + expf(-(acc.y * inv + bb.y + rr.y)));
    o.z = 1.f / (1.f + expf(-(acc.z * inv + bb.z + rr.z)));
    o.w = 1.f / (1.f + expf(-(acc.w * inv + bb.w + rr.w)));
    *(float4*)(out + (size_t)node * 128 + c) = o;
}

// ---------------- launch ---------------------------------------------------------
extern "C" void kernel_launch(void* const* d_in, const int* in_sizes, int n_in,
                              void* d_out, int out_size) {
    (void)in_sizes; (void)n_in; (void)out_size;
    const float* x   = (const float*)d_in[0];
    const void*  ei  = d_in[1];
    const float* W1l = (const float*)d_in[2];
    const float* b1  = (const float*)d_in[3];
    const float* W1r = (const float*)d_in[4];
    const float* W2l = (const float*)d_in[5];
    const float* b2  = (const float*)d_in[6];
    const float* W2r = (const float*)d_in[7];
    float* out = (float*)d_out;

    cudaFuncSetAttribute(k_gemm<1>, cudaFuncAttributeMaxDynamicSharedMemorySize, SMEM_DYN);
    cudaFuncSetAttribute(k_gemm<2>, cudaFuncAttributeMaxDynamicSharedMemorySize, SMEM_DYN);

    k_init<<<(NODES + 255) / 256, 256>>>();
    k_edges<<<(EDGES + 255) / 256, 256>>>(ei);
    k_alloc<<<(NODES + 255) / 256, 256>>>();
    k_fill<<<(EDGES + 255) / 256, 256>>>();
    k_wprep<<<(256 * 512 + 256 * 256 + 255) / 256, 256>>>(W1l, W1r, W2l, W2r);
    k_convh<<<(NODES * 32 + 255) / 256, 256>>>(x);
    k_gather1<<<(NODES * 32 + 255) / 256, 256>>>();
    dim3 grid_g(2, NTILES);
    k_gemm<1><<<grid_g, 256, SMEM_DYN>>>(b1);
    k_gemm<2><<<grid_g, 256, SMEM_DYN>>>(b1 /*unused*/);
    k_gather2_final<<<(NODES * 32 + 255) / 256, 256>>>(b2, out);
}

// round 13
// speedup vs baseline: 2.1679x; 1.0045x over previous
#include <cuda_runtime.h>
#include <cuda_fp16.h>
#include <math.h>
#include <stdint.h>

#define NODES 50000
#define NODES_PAD 50048            // 391 tiles * 128
#define EDGES 800000
#define NTILES 391

// ---------------- scratch (static device globals; no allocs allowed) ----------
// Pure fp16 pipeline: activations and weights quantized to fp16, fp32 accum.
__device__ __align__(128) unsigned char g_a1[(size_t)NODES_PAD * 1024]; // [N][512 f16]: [0,512)B agg, [512,1024)B x
__device__ __align__(128) unsigned char g_a2[(size_t)NODES_PAD * 512];  // [N][256 f16]: h
__device__ __align__(128) unsigned char g_b1[256 * 1024];               // [256 n][512 f16]: W1l;W1r transposed
__device__ __align__(128) unsigned char g_b2[256 * 512];                // [256 n][256 f16]: W2l|W2r transposed
__device__ __align__(128) unsigned char g_pl[(size_t)NODES_PAD * 256];  // [N][128 f16]: h@W2l (gathered later)
__device__ __align__(128) float g_pr[(size_t)NODES_PAD * 128];          // [N][128 f32]: h@W2r (self term)
__device__ int   g_cnt [NODES];
__device__ float g_inv [NODES];
__device__ int   g_src [EDGES];
__device__ int   g_dst [EDGES];
__device__ int   g_rank[EDGES];         // rank of edge within its dst bucket
__device__ int   g_off [NODES];
__device__ int   g_esrc[EDGES];
__device__ int   g_total;

// ---------------- PTX helpers ---------------------------------------------------
__device__ __forceinline__ uint32_t smem_u32(const void* p) {
    uint32_t a;
    asm("{ .reg .u64 t; cvta.to.shared.u64 t, %1; cvt.u32.u64 %0, t; }" : "=r"(a) : "l"(p));
    return a;
}
#define SW128(o) ((o) ^ (((o) >> 3) & 0x70))

__device__ __forceinline__ void cp16(uint32_t dst, const void* src) {
    asm volatile("cp.async.cg.shared.global [%0], [%1], 16;" :: "r"(dst), "l"(src));
}
#define CP_COMMIT() asm volatile("cp.async.commit_group;" ::: "memory")
#define CP_WAIT(n)  asm volatile("cp.async.wait_group %0;" :: "n"(n) : "memory")

__device__ __forceinline__ void ldsm4(uint32_t addr, uint32_t* r) {
    asm volatile("ldmatrix.sync.aligned.m8n8.x4.shared.b16 {%0,%1,%2,%3}, [%4];"
        : "=r"(r[0]), "=r"(r[1]), "=r"(r[2]), "=r"(r[3]) : "r"(addr));
}
__device__ __forceinline__ void mma16816(float* c, const uint32_t* a, uint32_t b0, uint32_t b1) {
    asm volatile("mma.sync.aligned.m16n8k16.row.col.f32.f16.f16.f32 "
        "{%0,%1,%2,%3}, {%4,%5,%6,%7}, {%8,%9}, {%0,%1,%2,%3};"
        : "+f"(c[0]), "+f"(c[1]), "+f"(c[2]), "+f"(c[3])
        : "r"(a[0]), "r"(a[1]), "r"(a[2]), "r"(a[3]), "r"(b0), "r"(b1));
}

__device__ __forceinline__ unsigned short f2h(float v) {
    __half h = __float2half_rn(v);
    return *reinterpret_cast<unsigned short*>(&h);
}
__device__ __forceinline__ uint32_t pack2h(float a, float b) {
    return (uint32_t)f2h(a) | ((uint32_t)f2h(b) << 16);
}
__device__ __forceinline__ float2 uph(uint32_t w) {
    return __half22float2(*reinterpret_cast<__half2*>(&w));
}

// ---------------- init ----------------------------------------------------------
__global__ void k_init() {
    int i = blockIdx.x * blockDim.x + threadIdx.x;
    if (i < NODES) g_cnt[i] = 0;
    if (i == 0) g_total = 0;
}

// ------- edge decode + degree count; atomic result IS the bucket rank ----------
__global__ void k_edges(const void* __restrict__ ei_raw) {
    int e = blockIdx.x * blockDim.x + threadIdx.x;
    if (e >= EDGES) return;
    const int* w = (const int*)ei_raw;
    bool is64 = ((w[1] | w[3] | w[5] | w[7] | w[9] | w[11] | w[13] | w[15]) == 0);
    int s, d;
    if (is64) {
        const long long* e64 = (const long long*)ei_raw;
        s = (int)e64[e];
        d = (int)e64[EDGES + e];
    } else {
        s = w[e];
        d = w[EDGES + e];
    }
    g_src[e] = s;
    g_dst[e] = d;
    g_rank[e] = atomicAdd(&g_cnt[d], 1);
}

// ------- bucket allocation: per-block scan + one global atomic; also 1/deg -----
__global__ void k_alloc() {
    __shared__ int s[256];
    __shared__ int base;
    int t = threadIdx.x;
    int i = blockIdx.x * 256 + t;
    int v = (i < NODES) ? g_cnt[i] : 0;
    s[t] = v;
    __syncthreads();
#pragma unroll
    for (int d = 1; d < 256; d <<= 1) {
        int add = (t >= d) ? s[t - d] : 0;
        __syncthreads();
        s[t] += add;
        __syncthreads();
    }
    int incl = s[t];
    if (t == 255) base = atomicAdd(&g_total, incl);
    __syncthreads();
    if (i < NODES) {
        g_off[i] = base + incl - v;
        g_inv[i] = 1.f / fmaxf((float)v, 1.f);
    }
}

// ------- bucket fill: atomic-free scatter via precomputed rank ------------------
__global__ void k_fill() {
    int e = blockIdx.x * blockDim.x + threadIdx.x;
    if (e >= EDGES) return;
    g_esrc[g_off[g_dst[e]] + g_rank[e]] = g_src[e];
}

// ------- fused prep: weights -> fp16 transposed streams, x -> fp16 copy ---------
#define WPREP_N (256 * 512 + 256 * 256)     // 196608
__global__ void k_prep(const float* __restrict__ W1l, const float* __restrict__ W1r,
                       const float* __restrict__ W2l, const float* __restrict__ W2r,
                       const float* __restrict__ x) {
    int id = blockIdx.x * blockDim.x + threadIdx.x;
    if (id < 256 * 512) {
        int n = id >> 9, k = id & 511;
        float w = (k < 256) ? W1l[k * 256 + n] : W1r[(k - 256) * 256 + n];
        *(unsigned short*)(g_b1 + (size_t)n * 1024 + 2 * k) = f2h(w);
    } else if (id < WPREP_N) {
        int id2 = id - 256 * 512;
        int n = id2 >> 8, k = id2 & 255;
        float w = (n < 128) ? W2l[k * 128 + n] : W2r[k * 128 + (n - 128)];
        *(unsigned short*)(g_b2 + (size_t)n * 512 + 2 * k) = f2h(w);
    } else if (id < WPREP_N + NODES * 32) {
        int id2 = id - WPREP_N;
        int node = id2 >> 5;
        int col  = (id2 & 31) * 8;
        const float4* src = (const float4*)(x + (size_t)node * 256 + col);
        float4 a = src[0], b = src[1];
        uint4 o;
        o.x = pack2h(a.x, a.y);
        o.y = pack2h(a.z, a.w);
        o.z = pack2h(b.x, b.y);
        o.w = pack2h(b.z, b.w);
        *(uint4*)(g_a1 + (size_t)node * 1024 + 512 + col * 2) = o;
    }
}

// ------------- layer-1 gather (fp16 rows, fp32 accumulate) -----------------------
// One warp per node; lane owns 8 cols (16B fp16); 4-edge unroll for MLP.
__global__ void k_gather1() {
    int node = (blockIdx.x * blockDim.x + threadIdx.x) >> 5;
    if (node >= NODES) return;
    int lane = threadIdx.x & 31;
    int boff = lane * 16;

    int e   = g_off[node];
    int end = e + g_cnt[node];
    float acc[8];
#pragma unroll
    for (int i = 0; i < 8; i++) acc[i] = 0.f;

    for (; e + 3 < end; e += 4) {
        int s0 = g_esrc[e], s1 = g_esrc[e + 1], s2 = g_esrc[e + 2], s3 = g_esrc[e + 3];
        uint4 v0 = *(const uint4*)(g_a1 + (size_t)s0 * 1024 + 512 + boff);
        uint4 v1 = *(const uint4*)(g_a1 + (size_t)s1 * 1024 + 512 + boff);
        uint4 v2 = *(const uint4*)(g_a1 + (size_t)s2 * 1024 + 512 + boff);
        uint4 v3 = *(const uint4*)(g_a1 + (size_t)s3 * 1024 + 512 + boff);
        float2 f;
        f = uph(v0.x); acc[0] += f.x; acc[1] += f.y;
        f = uph(v0.y); acc[2] += f.x; acc[3] += f.y;
        f = uph(v0.z); acc[4] += f.x; acc[5] += f.y;
        f = uph(v0.w); acc[6] += f.x; acc[7] += f.y;
        f = uph(v1.x); acc[0] += f.x; acc[1] += f.y;
        f = uph(v1.y); acc[2] += f.x; acc[3] += f.y;
        f = uph(v1.z); acc[4] += f.x; acc[5] += f.y;
        f = uph(v1.w); acc[6] += f.x; acc[7] += f.y;
        f = uph(v2.x); acc[0] += f.x; acc[1] += f.y;
        f = uph(v2.y); acc[2] += f.x; acc[3] += f.y;
        f = uph(v2.z); acc[4] += f.x; acc[5] += f.y;
        f = uph(v2.w); acc[6] += f.x; acc[7] += f.y;
        f = uph(v3.x); acc[0] += f.x; acc[1] += f.y;
        f = uph(v3.y); acc[2] += f.x; acc[3] += f.y;
        f = uph(v3.z); acc[4] += f.x; acc[5] += f.y;
        f = uph(v3.w); acc[6] += f.x; acc[7] += f.y;
    }
    for (; e < end; e++) {
        int s0 = g_esrc[e];
        uint4 v0 = *(const uint4*)(g_a1 + (size_t)s0 * 1024 + 512 + boff);
        float2 f;
        f = uph(v0.x); acc[0] += f.x; acc[1] += f.y;
        f = uph(v0.y); acc[2] += f.x; acc[3] += f.y;
        f = uph(v0.z); acc[4] += f.x; acc[5] += f.y;
        f = uph(v0.w); acc[6] += f.x; acc[7] += f.y;
    }
    float inv = g_inv[node];
    uint4 o;
    o.x = pack2h(acc[0] * inv, acc[1] * inv);
    o.y = pack2h(acc[2] * inv, acc[3] * inv);
    o.z = pack2h(acc[4] * inv, acc[5] * inv);
    o.w = pack2h(acc[6] * inv, acc[7] * inv);
    *(uint4*)(g_a1 + (size_t)node * 1024 + boff) = o;
}

// ---------------- warp-MMA fp16 GEMM: D[128 rows, 128 cols] per CTA --------------
// MODE 1: A=g_a1 (K=512, 8 tiles), B=g_b1; epilogue bias+relu -> g_a2 fp16
// MODE 2: A=g_a2 (K=256, 4 tiles), B=g_b2; epilogue: left->g_pl fp16, right->g_pr f32
#define STAGE_BYTES 32768                 // A 16KB + B 16KB
#define SMEM_DYN (3 * STAGE_BYTES)

template <int MODE>
__global__ __launch_bounds__(256, 2) void k_gemm(const float* __restrict__ bias) {
    constexpr int RB = (MODE == 1) ? 1024 : 512;    // stream row bytes
    constexpr int KT = (MODE == 1) ? 8 : 4;         // 128-byte k-tiles (64 f16)
    const unsigned char* gA = (MODE == 1) ? g_a1 : g_a2;
    const unsigned char* gB = (MODE == 1) ? g_b1 : g_b2;

    extern __shared__ __align__(128) unsigned char dsm[];
    const int t      = threadIdx.x;
    const int lane   = t & 31;
    const int wid    = t >> 5;
    const int warp_m = wid & 3;
    const int warp_n = wid >> 2;
    const int row0   = blockIdx.y * 128;
    const int col0   = blockIdx.x * 128;
    const uint32_t base = smem_u32(dsm);

    float c[2][8][4];
#pragma unroll
    for (int i = 0; i < 2; i++)
#pragma unroll
        for (int j = 0; j < 8; j++)
#pragma unroll
            for (int q = 0; q < 4; q++) c[i][j][q] = 0.f;

    const int lrow = t >> 1;
    const int ch0  = (t & 1) * 4;

    auto load_tile = [&](int kt, int s) {
        uint32_t sa = base + s * STAGE_BYTES;
        uint32_t sb = sa + 16384;
        const unsigned char* srcA = gA + (size_t)(row0 + lrow) * RB + (size_t)kt * 128 + ch0 * 16;
#pragma unroll
        for (int i = 0; i < 4; i++)
            cp16(sa + SW128(lrow * 128 + (ch0 + i) * 16), srcA + i * 16);
        const unsigned char* srcB = gB + (size_t)(col0 + lrow) * RB + (size_t)kt * 128 + ch0 * 16;
#pragma unroll
        for (int i = 0; i < 4; i++)
            cp16(sb + SW128(lrow * 128 + (ch0 + i) * 16), srcB + i * 16);
        CP_COMMIT();
    };

    const int lj = lane >> 3;
    const int lr = lane & 7;

    auto compute = [&](int s) {
        uint32_t sa = base + s * STAGE_BYTES;
        uint32_t sb = sa + 16384;
#pragma unroll
        for (int ks = 0; ks < 4; ks++) {
            int cb = ks * 32 + (lj >> 1) * 16;
            uint32_t af[2][4];
#pragma unroll
            for (int mm = 0; mm < 2; mm++) {
                int row = warp_m * 32 + mm * 16 + (lj & 1) * 8 + lr;
                ldsm4(sa + SW128(row * 128 + cb), af[mm]);
            }
            uint32_t bf[4][4];
#pragma unroll
            for (int np = 0; np < 4; np++) {
                int row = warp_n * 64 + np * 16 + (lj & 1) * 8 + lr;
                ldsm4(sb + SW128(row * 128 + cb), bf[np]);
            }
#pragma unroll
            for (int mm = 0; mm < 2; mm++)
#pragma unroll
                for (int nn = 0; nn < 8; nn++)
                    mma16816(c[mm][nn], af[mm], bf[nn >> 1][nn & 1], bf[nn >> 1][(nn & 1) + 2]);
        }
    };

    load_tile(0, 0);
    load_tile(1, 1);
#pragma unroll 1
    for (int kt = 0; kt < KT; kt++) {
        if (kt == KT - 1) { CP_WAIT(0); } else { CP_WAIT(1); }
        __syncthreads();
        if (kt + 2 < KT) load_tile(kt + 2, (kt + 2) % 3);
        compute(kt % 3);
    }

    // ---------------- epilogue -------------------------------------------------
    const int qr = lane >> 2;
    const int qc = (lane & 3) * 2;
#pragma unroll
    for (int mm = 0; mm < 2; mm++) {
#pragma unroll
        for (int nn = 0; nn < 8; nn++) {
            int col = col0 + warp_n * 64 + nn * 8 + qc;
#pragma unroll
            for (int h = 0; h < 2; h++) {
                int row = row0 + warp_m * 32 + mm * 16 + qr + h * 8;
                float v0 = c[mm][nn][2 * h + 0];
                float v1 = c[mm][nn][2 * h + 1];
                if (MODE == 1) {
                    v0 = fmaxf(v0 + __ldg(&bias[col]), 0.f);
                    v1 = fmaxf(v1 + __ldg(&bias[col + 1]), 0.f);
                    *(uint32_t*)(g_a2 + (size_t)row * 512 + 2 * col) = pack2h(v0, v1);
                } else {
                    if (col < 128) {
                        *(uint32_t*)(g_pl + (size_t)row * 256 + 2 * col) = pack2h(v0, v1);
                    } else {
                        *(float2*)(g_pr + (size_t)row * 128 + (col - 128)) = make_float2(v0, v1);
                    }
                }
            }
        }
    }
}

// ---- layer-2 gather fused with epilogue: out = sigmoid(mean(p_l)+b2+p_r) -------
// One warp per node; lane owns 4 cols (8B fp16 per edge); 4-edge unroll.
__global__ void k_gather2_final(const float* __restrict__ b2,
                                float* __restrict__ out) {
    int node = (blockIdx.x * blockDim.x + threadIdx.x) >> 5;
    if (node >= NODES) return;
    int lane = threadIdx.x & 31;
    int c = lane * 4;

    int e   = g_off[node];
    int end = e + g_cnt[node];
    float4 acc = make_float4(0.f, 0.f, 0.f, 0.f);
    for (; e + 3 < end; e += 4) {
        int s0 = g_esrc[e], s1 = g_esrc[e + 1], s2 = g_esrc[e + 2], s3 = g_esrc[e + 3];
        uint2 v0 = *(const uint2*)(g_pl + (size_t)s0 * 256 + 2 * c);
        uint2 v1 = *(const uint2*)(g_pl + (size_t)s1 * 256 + 2 * c);
        uint2 v2 = *(const uint2*)(g_pl + (size_t)s2 * 256 + 2 * c);
        uint2 v3 = *(const uint2*)(g_pl + (size_t)s3 * 256 + 2 * c);
        float2 f;
        f = uph(v0.x); acc.x += f.x; acc.y += f.y;
        f = uph(v0.y); acc.z += f.x; acc.w += f.y;
        f = uph(v1.x); acc.x += f.x; acc.y += f.y;
        f = uph(v1.y); acc.z += f.x; acc.w += f.y;
        f = uph(v2.x); acc.x += f.x; acc.y += f.y;
        f = uph(v2.y); acc.z += f.x; acc.w += f.y;
        f = uph(v3.x); acc.x += f.x; acc.y += f.y;
        f = uph(v3.y); acc.z += f.x; acc.w += f.y;
    }
    for (; e < end; e++) {
        int s0 = g_esrc[e];
        uint2 v0 = *(const uint2*)(g_pl + (size_t)s0 * 256 + 2 * c);
        float2 f;
        f = uph(v0.x); acc.x += f.x; acc.y += f.y;
        f = uph(v0.y); acc.z += f.x; acc.w += f.y;
    }
    float inv = g_inv[node];
    float4 bb = *(const float4*)(b2 + c);
    float4 rr = *(const float4*)(g_pr + (size_t)node * 128 + c);
    float4 o;
    o.x = 1.f / (1.f + expf(-(acc.x * inv + bb.x + rr.x)));
    o.y = 1.f / (1.f + expf(-(acc.y * inv + bb.y + rr.y)));
    o.z = 1.f / (1.f + expf(-(acc.z * inv + bb.z + rr.z)));
    o.w = 1.f / (1.f + expf(-(acc.w * inv + bb.w + rr.w)));
    *(float4*)(out + (size_t)node * 128 + c) = o;
}

// ---------------- launch ---------------------------------------------------------
extern "C" void kernel_launch(void* const* d_in, const int* in_sizes, int n_in,
                              void* d_out, int out_size) {
    (void)in_sizes; (void)n_in; (void)out_size;
    const float* x   = (const float*)d_in[0];
    const void*  ei  = d_in[1];
    const float* W1l = (const float*)d_in[2];
    const float* b1  = (const float*)d_in[3];
    const float* W1r = (const float*)d_in[4];
    const float* W2l = (const float*)d_in[5];
    const float* b2  = (const float*)d_in[6];
    const float* W2r = (const float*)d_in[7];
    float* out = (float*)d_out;

    cudaFuncSetAttribute(k_gemm<1>, cudaFuncAttributeMaxDynamicSharedMemorySize, SMEM_DYN);
    cudaFuncSetAttribute(k_gemm<2>, cudaFuncAttributeMaxDynamicSharedMemorySize, SMEM_DYN);

    k_init<<<(NODES + 255) / 256, 256>>>();
    k_edges<<<(EDGES + 255) / 256, 256>>>(ei);
    k_alloc<<<(NODES + 255) / 256, 256>>>();
    k_fill<<<(EDGES + 255) / 256, 256>>>();
    k_prep<<<(WPREP_N + NODES * 32 + 255) / 256, 256>>>(W1l, W1r, W2l, W2r, x);
    k_gather1<<<(NODES * 32 + 255) / 256, 256>>>();
    dim3 grid_g(2, NTILES);
    k_gemm<1><<<grid_g, 256, SMEM_DYN>>>(b1);
    k_gemm<2><<<grid_g, 256, SMEM_DYN>>>(b1 /*unused*/);
    k_gather2_final<<<(NODES * 32 + 255) / 256, 256>>>(b2, out);
}